// round 11
// baseline (speedup 1.0000x reference)
#include <cuda_runtime.h>
#include <cuda_fp16.h>

typedef unsigned int u32;

#define NROWS    16384
#define DIM      4096
#define NEXP     64
#define KT       64
#define NCHUNK   (DIM / KT)
#define ROWS_CTA 64             // halved: 2 CTAs per SM
#define NTH      256            // 8 warps
#define NCTA     (NROWS / ROWS_CTA)   // 256

#define WSCALE     4096.0f
#define INV_WSCALE (1.0f / 4096.0f)
#define RSC        2048.0f
#define RINV       (1.0f / 2048.0f)

// smem layout (bytes)
#define A_COMP   8192           // 64 rows x 128B
#define A_STAGE  16384
#define OFF_B    32768
#define B_COMP   8192           // 64 experts x 128B
#define B_STAGE  16384
#define OFF_BIAS 65536
#define SMEM_BYTES 65792

#define SWZ(o) ((o) ^ (((o) >> 3) & 0x70))

// W pre-split: comp0 = fp16(W*4096), comp1 = fp16((W*4096 - comp0)*2048)
__device__ __half g_Wc[2][NEXP * DIM];

// ---------------- helpers ----------------
__device__ __forceinline__ u32 smem_u32(const void* p) {
    u32 a;
    asm("{ .reg .u64 t; cvta.to.shared.u64 t, %1; cvt.u32.u64 %0, t; }" : "=r"(a) : "l"(p));
    return a;
}

__device__ __forceinline__ void ldsm4(u32* r, u32 addr) {
    asm volatile("ldmatrix.sync.aligned.m8n8.x4.shared.b16 {%0,%1,%2,%3}, [%4];"
                 : "=r"(r[0]), "=r"(r[1]), "=r"(r[2]), "=r"(r[3]) : "r"(addr));
}

__device__ __forceinline__ void mma16816(float* d, const u32* a, u32 b0, u32 b1) {
    asm volatile(
        "mma.sync.aligned.m16n8k16.row.col.f32.f16.f16.f32 "
        "{%0,%1,%2,%3}, {%4,%5,%6,%7}, {%8,%9}, {%0,%1,%2,%3};"
        : "+f"(d[0]), "+f"(d[1]), "+f"(d[2]), "+f"(d[3])
        : "r"(a[0]), "r"(a[1]), "r"(a[2]), "r"(a[3]), "r"(b0), "r"(b1));
}

// split float4 -> hi fp16 comp + UP-SCALED fp16 residual comp
__device__ __forceinline__ void split4(float4 v, uint2& h1, uint2& h2) {
    __half2 p0 = __floats2half2_rn(v.x, v.y);
    __half2 p1 = __floats2half2_rn(v.z, v.w);
    float2 f0 = __half22float2(p0);
    float2 f1 = __half22float2(p1);
    __half2 q0 = __floats2half2_rn((v.x - f0.x) * RSC, (v.y - f0.y) * RSC);
    __half2 q1 = __floats2half2_rn((v.z - f1.x) * RSC, (v.w - f1.y) * RSC);
    h1.x = reinterpret_cast<u32&>(p0);
    h1.y = reinterpret_cast<u32&>(p1);
    h2.x = reinterpret_cast<u32&>(q0);
    h2.y = reinterpret_cast<u32&>(q1);
}

// ---------------- prep: split scaled W into 2 fp16 components ----------------
__global__ void prep_kernel(const float* __restrict__ W) {
    int total = NEXP * DIM / 4;
    for (int idx = blockIdx.x * blockDim.x + threadIdx.x; idx < total;
         idx += gridDim.x * blockDim.x) {
        float4 v = ((const float4*)W)[idx];
        v.x *= WSCALE; v.y *= WSCALE; v.z *= WSCALE; v.w *= WSCALE;
        uint2 h1, h2;
        split4(v, h1, h2);
        ((uint2*)g_Wc[0])[idx] = h1;
        ((uint2*)g_Wc[1])[idx] = h2;
    }
}

// ---------------- main fused kernel ----------------
__global__ __launch_bounds__(NTH, 2)
void gating_mma_kernel(const float* __restrict__ x, const float* __restrict__ bias_g,
                       float* __restrict__ out, int out_size)
{
    extern __shared__ char smem[];
    const u32 sb = smem_u32(smem);
    const int tid = threadIdx.x;
    const int lane = tid & 31;
    const int warp = tid >> 5;
    const int rowBase = blockIdx.x * ROWS_CTA;

    // warp tile m16n32: 4 row-groups x 2 col-groups (8 warps cover 64x64)
    const int mrow = (warp & 3) * 16;
    const int ncol = (warp >> 2) * 32;

    if (tid < NEXP) ((float*)(smem + OFF_BIAS))[tid] = bias_g[tid];

    // per-thread load shares: A = 1024 float4 (64 rows x 16), W = 1024 uint4
    const int xr = tid >> 4, xq = tid & 15;            // + i*16 rows
    const u32 a_sts_base = SWZ((u32)(xr * 128 + xq * 8));
    int wcc[4], wee[4], wqq[4];
    u32 b_sts[4];
#pragma unroll
    for (int i = 0; i < 4; i++) {
        int wi = tid + i * NTH;
        wcc[i] = wi >> 9; wee[i] = (wi & 511) >> 3; wqq[i] = wi & 7;
        b_sts[i] = (u32)(wcc[i] * B_COMP) + SWZ((u32)(wee[i] * 128 + wqq[i] * 16));
    }

    float4 px[4];
    uint4  pw[4];

    // ---- prologue: LDG chunk 0 ----
#pragma unroll
    for (int i = 0; i < 4; i++)
        px[i] = *(const float4*)(x + (size_t)(rowBase + xr + i * 16) * DIM + xq * 4);
#pragma unroll
    for (int i = 0; i < 4; i++)
        pw[i] = *(const uint4*)(&g_Wc[wcc[i]][(size_t)wee[i] * DIM + wqq[i] * 8]);

    // accumulators
    float accm[4][4], accc[4][4];
#pragma unroll
    for (int nt = 0; nt < 4; nt++)
#pragma unroll
        for (int j = 0; j < 4; j++) { accm[nt][j] = 0.0f; accc[nt][j] = 0.0f; }

    // ldmatrix lane geometry
    const int a_row  = lane & 15;
    const int a_koff = (lane >> 4) * 8;
    const int g  = lane >> 3, lr = lane & 7;
    const int be  = ((g >= 2) ? 8 : 0) + lr;
    const int bko = (g & 1) ? 16 : 0;

    for (int c = 0; c < NCHUNK; c++) {
        const int st = c & 1;
        char* As = smem + st * A_STAGE;
        char* Bs = smem + OFF_B + st * B_STAGE;

        // ---- STS chunk c (from regs), swizzled ----
#pragma unroll
        for (int i = 0; i < 4; i++) {
            uint2 h1, h2;
            split4(px[i], h1, h2);
            *(uint2*)(As + (a_sts_base + i * 2048)) = h1;
            *(uint2*)(As + A_COMP + (a_sts_base + i * 2048)) = h2;
        }
#pragma unroll
        for (int i = 0; i < 4; i++)
            *(uint4*)(Bs + b_sts[i]) = pw[i];
        __syncthreads();

        // ---- LDG chunk c+1 -> regs (hidden behind mma) ----
        if (c + 1 < NCHUNK) {
            const int k0 = (c + 1) * KT;
            const float* xc = x + (size_t)rowBase * DIM + k0;
#pragma unroll
            for (int i = 0; i < 4; i++)
                px[i] = *(const float4*)(xc + (size_t)(xr + i * 16) * DIM + xq * 4);
#pragma unroll
            for (int i = 0; i < 4; i++)
                pw[i] = *(const uint4*)(&g_Wc[wcc[i]][(size_t)wee[i] * DIM + k0 + wqq[i] * 8]);
        }

        // ---- mma on stage st ----
        const u32 sA  = sb + st * A_STAGE;
        const u32 sB1 = sb + OFF_B + st * B_STAGE;
        const u32 sB2 = sB1 + B_COMP;
#pragma unroll
        for (int kc = 0; kc < 4; kc++) {
            u32 a1[4], a2[4];
            {
                u32 off = SWZ((u32)((mrow + a_row) * 128 + kc * 32 + a_koff * 2));
                ldsm4(a1, sA + off);
                ldsm4(a2, sA + A_COMP + off);
            }
            u32 b1[2][4], b2[2][4];
#pragma unroll
            for (int p = 0; p < 2; p++) {
                u32 off = SWZ((u32)((ncol + p * 16 + be) * 128 + kc * 32 + bko));
                ldsm4(b1[p], sB1 + off);
                ldsm4(b2[p], sB2 + off);
            }
#pragma unroll
            for (int nt = 0; nt < 4; nt++) {
                int p = nt >> 1, o = (nt & 1) * 2;
                mma16816(accm[nt], a1, b1[p][o], b1[p][o + 1]);
            }
#pragma unroll
            for (int nt = 0; nt < 4; nt++) {
                int p = nt >> 1, o = (nt & 1) * 2;
                mma16816(accc[nt], a1, b2[p][o], b2[p][o + 1]);
            }
#pragma unroll
            for (int nt = 0; nt < 4; nt++) {
                int p = nt >> 1, o = (nt & 1) * 2;
                mma16816(accc[nt], a2, b1[p][o], b1[p][o + 1]);
            }
        }
        __syncthreads();
    }

    // ---- epilogue: combine accumulators, logits -> smem overlay, fused top-2 ----
    float (*lg)[66] = (float(*)[66])smem;   // 64 x 66 f32 = 16896B (fits stage 0)
#pragma unroll
    for (int nt = 0; nt < 4; nt++) {
        int r0 = mrow + (lane >> 2);
        int cb = ncol + nt * 8 + 2 * (lane & 3);
        float c0 = fmaf(accc[nt][0], RINV, accm[nt][0]);
        float c1 = fmaf(accc[nt][1], RINV, accm[nt][1]);
        float c2 = fmaf(accc[nt][2], RINV, accm[nt][2]);
        float c3 = fmaf(accc[nt][3], RINV, accm[nt][3]);
        *(float2*)&lg[r0][cb]     = make_float2(c0, c1);
        *(float2*)&lg[r0 + 8][cb] = make_float2(c2, c3);
    }
    __syncthreads();

    if (tid < ROWS_CTA) {
        const float* bs = (const float*)(smem + OFF_BIAS);
        float v0 = -3.402823466e38f, v1 = -3.402823466e38f;
        int i0 = 0, i1 = 0;
#pragma unroll
        for (int e = 0; e < NEXP; e++) {
            float v = fmaf(lg[tid][e], INV_WSCALE, bs[e]);
            if (v > v0) { v1 = v0; i1 = i0; v0 = v; i0 = e; }
            else if (v > v1) { v1 = v; i1 = e; }
        }
        float d  = expf(v1 - v0);
        float p0 = 1.0f / (1.0f + d);
        float p1 = d / (1.0f + d);

        int grow = rowBase + tid;
        float* orow = out + (size_t)grow * NEXP;
#pragma unroll
        for (int gq = 0; gq < NEXP / 4; gq++) {
            float4 ov;
            int e = gq * 4;
            ov.x = (e + 0 == i0) ? p0 : ((e + 0 == i1) ? p1 : 0.0f);
            ov.y = (e + 1 == i0) ? p0 : ((e + 1 == i1) ? p1 : 0.0f);
            ov.z = (e + 2 == i0) ? p0 : ((e + 2 == i1) ? p1 : 0.0f);
            ov.w = (e + 3 == i0) ? p0 : ((e + 3 == i1) ? p1 : 0.0f);
            *(float4*)(orow + e) = ov;
        }
        if (out_size >= NROWS * (NEXP + 2)) {
            float* oidx = out + (size_t)NROWS * NEXP + (size_t)grow * 2;
            oidx[0] = (float)i0;
            oidx[1] = (float)i1;
        }
    }
}

extern "C" void kernel_launch(void* const* d_in, const int* in_sizes, int n_in,
                              void* d_out, int out_size) {
    const float* x = nullptr;
    const float* W = nullptr;
    const float* b = nullptr;
    for (int i = 0; i < n_in; i++) {
        if (in_sizes[i] == NROWS * DIM)      x = (const float*)d_in[i];
        else if (in_sizes[i] == NEXP * DIM)  W = (const float*)d_in[i];
        else if (in_sizes[i] == NEXP)        b = (const float*)d_in[i];
    }
    cudaFuncSetAttribute(gating_mma_kernel, cudaFuncAttributeMaxDynamicSharedMemorySize,
                         SMEM_BYTES);
    prep_kernel<<<128, 256>>>(W);
    gating_mma_kernel<<<NCTA, NTH, SMEM_BYTES>>>(x, b, (float*)d_out, out_size);
}

// round 12
// speedup vs baseline: 1.2061x; 1.2061x over previous
#include <cuda_runtime.h>
#include <cuda_fp16.h>

typedef unsigned int u32;

#define NROWS    16384
#define DIM      4096
#define NEXP     64
#define KT       64
#define NCHUNK   (DIM / KT)
#define ROWS_CTA 128
#define NTH      256            // 8 warps, m32n32 per warp (smem-efficient shape)

#define WSCALE     4096.0f
#define INV_WSCALE (1.0f / 4096.0f)
#define RSC        2048.0f
#define RINV       (1.0f / 2048.0f)

// smem layout (bytes)
#define A_COMP   16384
#define A_STAGE  32768
#define OFF_B    65536
#define B_COMP   8192
#define B_STAGE  16384
#define OFF_BIAS 98304
#define SMEM_BYTES 98560

#define SWZ(o) ((o) ^ (((o) >> 3) & 0x70))

// W pre-split: comp0 = fp16(W*4096), comp1 = fp16((W*4096 - comp0)*2048)
__device__ __half g_Wc[2][NEXP * DIM];

// ---------------- helpers ----------------
__device__ __forceinline__ u32 smem_u32(const void* p) {
    u32 a;
    asm("{ .reg .u64 t; cvta.to.shared.u64 t, %1; cvt.u32.u64 %0, t; }" : "=r"(a) : "l"(p));
    return a;
}

__device__ __forceinline__ void ldsm4(u32* r, u32 addr) {
    asm volatile("ldmatrix.sync.aligned.m8n8.x4.shared.b16 {%0,%1,%2,%3}, [%4];"
                 : "=r"(r[0]), "=r"(r[1]), "=r"(r[2]), "=r"(r[3]) : "r"(addr));
}

__device__ __forceinline__ void mma16816(float* d, const u32* a, u32 b0, u32 b1) {
    asm volatile(
        "mma.sync.aligned.m16n8k16.row.col.f32.f16.f16.f32 "
        "{%0,%1,%2,%3}, {%4,%5,%6,%7}, {%8,%9}, {%0,%1,%2,%3};"
        : "+f"(d[0]), "+f"(d[1]), "+f"(d[2]), "+f"(d[3])
        : "r"(a[0]), "r"(a[1]), "r"(a[2]), "r"(a[3]), "r"(b0), "r"(b1));
}

// split float4 -> hi fp16 comp + UP-SCALED fp16 residual comp
__device__ __forceinline__ void split4(float4 v, uint2& h1, uint2& h2) {
    __half2 p0 = __floats2half2_rn(v.x, v.y);
    __half2 p1 = __floats2half2_rn(v.z, v.w);
    float2 f0 = __half22float2(p0);
    float2 f1 = __half22float2(p1);
    __half2 q0 = __floats2half2_rn((v.x - f0.x) * RSC, (v.y - f0.y) * RSC);
    __half2 q1 = __floats2half2_rn((v.z - f1.x) * RSC, (v.w - f1.y) * RSC);
    h1.x = reinterpret_cast<u32&>(p0);
    h1.y = reinterpret_cast<u32&>(p1);
    h2.x = reinterpret_cast<u32&>(q0);
    h2.y = reinterpret_cast<u32&>(q1);
}

// ---------------- prep: split scaled W into 2 fp16 components ----------------
__global__ void prep_kernel(const float* __restrict__ W) {
    int total = NEXP * DIM / 4;
    for (int idx = blockIdx.x * blockDim.x + threadIdx.x; idx < total;
         idx += gridDim.x * blockDim.x) {
        float4 v = ((const float4*)W)[idx];
        v.x *= WSCALE; v.y *= WSCALE; v.z *= WSCALE; v.w *= WSCALE;
        uint2 h1, h2;
        split4(v, h1, h2);
        ((uint2*)g_Wc[0])[idx] = h1;
        ((uint2*)g_Wc[1])[idx] = h2;
    }
}

// ---------------- main fused kernel ----------------
__global__ __launch_bounds__(NTH, 1)
void gating_mma_kernel(const float* __restrict__ x, const float* __restrict__ bias_g,
                       float* __restrict__ out, int out_size)
{
    extern __shared__ char smem[];
    const u32 sb = smem_u32(smem);
    const int tid = threadIdx.x;
    const int lane = tid & 31;
    const int warp = tid >> 5;
    const int rowBase = blockIdx.x * ROWS_CTA;

    // warp tile m32n32: 4 row-groups x 2 col-groups
    const int mrow = (warp & 3) * 32;
    const int ncol = (warp >> 2) * 32;

    if (tid < NEXP) ((float*)(smem + OFF_BIAS))[tid] = bias_g[tid];

    // per-thread load shares (256 thr): A = 2048 float4 -> 8 ea; W = 1024 uint4 -> 4 ea
    const int xr = tid >> 4, xq = tid & 15;     // + i*16 rows (i<8 -> rows 0..127)
    const u32 a_sts_base = SWZ((u32)(xr * 128 + xq * 8));
    int wcc[4], wee[4], wqq[4];
    u32 b_sts[4];
#pragma unroll
    for (int i = 0; i < 4; i++) {
        int wi = tid + i * NTH;
        wcc[i] = wi >> 9; wee[i] = (wi & 511) >> 3; wqq[i] = wi & 7;
        b_sts[i] = (u32)(wcc[i] * B_COMP) + SWZ((u32)(wee[i] * 128 + wqq[i] * 16));
    }

    float4 px[8];
    uint4  pw[4];

    // ---- prologue: LDG c0; STS c0 -> stage 0; LDG c1; barrier ----
#pragma unroll
    for (int i = 0; i < 8; i++)
        px[i] = *(const float4*)(x + (size_t)(rowBase + xr + i * 16) * DIM + xq * 4);
#pragma unroll
    for (int i = 0; i < 4; i++)
        pw[i] = *(const uint4*)(&g_Wc[wcc[i]][(size_t)wee[i] * DIM + wqq[i] * 8]);

    {
        char* As = smem;
        char* Bs = smem + OFF_B;
#pragma unroll
        for (int i = 0; i < 8; i++) {
            uint2 h1, h2;
            split4(px[i], h1, h2);
            *(uint2*)(As + (a_sts_base + i * 2048)) = h1;
            *(uint2*)(As + A_COMP + (a_sts_base + i * 2048)) = h2;
        }
#pragma unroll
        for (int i = 0; i < 4; i++)
            *(uint4*)(Bs + b_sts[i]) = pw[i];
    }
#pragma unroll
    for (int i = 0; i < 8; i++)
        px[i] = *(const float4*)(x + (size_t)(rowBase + xr + i * 16) * DIM + KT + xq * 4);
#pragma unroll
    for (int i = 0; i < 4; i++)
        pw[i] = *(const uint4*)(&g_Wc[wcc[i]][(size_t)wee[i] * DIM + KT + wqq[i] * 8]);
    __syncthreads();

    // accumulators (m32n32: [mt][nt][4])
    float accm[2][4][4], accc[2][4][4];
#pragma unroll
    for (int mt = 0; mt < 2; mt++)
#pragma unroll
        for (int nt = 0; nt < 4; nt++)
#pragma unroll
            for (int j = 0; j < 4; j++) { accm[mt][nt][j] = 0.0f; accc[mt][nt][j] = 0.0f; }

    // ldmatrix lane geometry (A: m16k16; B: R6-verified mapping)
    const int a_row  = lane & 15;
    const int a_koff = (lane >> 4) * 8;
    const int g  = lane >> 3, lr = lane & 7;
    const int be  = ((g >= 2) ? 8 : 0) + lr;
    const int bko = (g & 1) ? 16 : 0;

    // fragment double-buffers: [buf][mt or p][4]
    u32 a1f[2][2][4], a2f[2][2][4], b1f[2][2][4], b2f[2][2][4];

    // ---- mainloop: 1 barrier/chunk; frag prefetch pipelines the kc loop ----
    for (int c = 0; c < NCHUNK; c++) {
        const int st = c & 1;
        const int sn = st ^ 1;
        const u32 sA  = sb + st * A_STAGE;
        const u32 sB1 = sb + OFF_B + st * B_STAGE;
        const u32 sB2 = sB1 + B_COMP;

        // preload kc=0 fragments into buf 0
        {
            u32 oa0 = SWZ((u32)((mrow + a_row) * 128 + a_koff * 2));
            u32 oa1 = SWZ((u32)((mrow + 16 + a_row) * 128 + a_koff * 2));
            ldsm4(a1f[0][0], sA + oa0);
            ldsm4(a1f[0][1], sA + oa1);
            ldsm4(a2f[0][0], sA + A_COMP + oa0);
            ldsm4(a2f[0][1], sA + A_COMP + oa1);
            u32 ob0 = SWZ((u32)((ncol + be) * 128 + bko));
            u32 ob1 = SWZ((u32)((ncol + 16 + be) * 128 + bko));
            ldsm4(b1f[0][0], sB1 + ob0);
            ldsm4(b1f[0][1], sB1 + ob1);
            ldsm4(b2f[0][0], sB2 + ob0);
            ldsm4(b2f[0][1], sB2 + ob1);
        }

#pragma unroll
        for (int kc = 0; kc < 4; kc++) {
            const int cur = kc & 1, nxt = cur ^ 1;
            // prefetch kc+1 fragments (latency hidden behind 24 mma below)
            if (kc < 3) {
                u32 oa0 = SWZ((u32)((mrow + a_row) * 128 + (kc + 1) * 32 + a_koff * 2));
                u32 oa1 = SWZ((u32)((mrow + 16 + a_row) * 128 + (kc + 1) * 32 + a_koff * 2));
                ldsm4(a1f[nxt][0], sA + oa0);
                ldsm4(a1f[nxt][1], sA + oa1);
                ldsm4(a2f[nxt][0], sA + A_COMP + oa0);
                ldsm4(a2f[nxt][1], sA + A_COMP + oa1);
                u32 ob0 = SWZ((u32)((ncol + be) * 128 + (kc + 1) * 32 + bko));
                u32 ob1 = SWZ((u32)((ncol + 16 + be) * 128 + (kc + 1) * 32 + bko));
                ldsm4(b1f[nxt][0], sB1 + ob0);
                ldsm4(b1f[nxt][1], sB1 + ob1);
                ldsm4(b2f[nxt][0], sB2 + ob0);
                ldsm4(b2f[nxt][1], sB2 + ob1);
            }
            // 24 mma on buf cur (fragments ready since previous kc)
#pragma unroll
            for (int mt = 0; mt < 2; mt++)
#pragma unroll
                for (int nt = 0; nt < 4; nt++) {
                    int p = nt >> 1, o = (nt & 1) * 2;
                    mma16816(accm[mt][nt], a1f[cur][mt], b1f[cur][p][o], b1f[cur][p][o + 1]);
                }
#pragma unroll
            for (int mt = 0; mt < 2; mt++)
#pragma unroll
                for (int nt = 0; nt < 4; nt++) {
                    int p = nt >> 1, o = (nt & 1) * 2;
                    mma16816(accc[mt][nt], a1f[cur][mt], b2f[cur][p][o], b2f[cur][p][o + 1]);
                }
#pragma unroll
            for (int mt = 0; mt < 2; mt++)
#pragma unroll
                for (int nt = 0; nt < 4; nt++) {
                    int p = nt >> 1, o = (nt & 1) * 2;
                    mma16816(accc[mt][nt], a2f[cur][mt], b1f[cur][p][o], b1f[cur][p][o + 1]);
                }
        }

        // STS chunk c+1 into stage sn (px/pw loaded one iteration ago)
        if (c + 1 < NCHUNK) {
            char* As = smem + sn * A_STAGE;
            char* Bs = smem + OFF_B + sn * B_STAGE;
#pragma unroll
            for (int i = 0; i < 8; i++) {
                uint2 h1, h2;
                split4(px[i], h1, h2);
                *(uint2*)(As + (a_sts_base + i * 2048)) = h1;
                *(uint2*)(As + A_COMP + (a_sts_base + i * 2048)) = h2;
            }
#pragma unroll
            for (int i = 0; i < 4; i++)
                *(uint4*)(Bs + b_sts[i]) = pw[i];
        }

        // LDG chunk c+2 -> regs
        if (c + 2 < NCHUNK) {
            const int k0 = (c + 2) * KT;
            const float* xc = x + (size_t)rowBase * DIM + k0;
#pragma unroll
            for (int i = 0; i < 8; i++)
                px[i] = *(const float4*)(xc + (size_t)(xr + i * 16) * DIM + xq * 4);
#pragma unroll
            for (int i = 0; i < 4; i++)
                pw[i] = *(const uint4*)(&g_Wc[wcc[i]][(size_t)wee[i] * DIM + k0 + wqq[i] * 8]);
        }

        __syncthreads();
    }

    // ---- epilogue: combine accumulators, logits -> smem overlay, fused top-2 ----
    float (*lg)[66] = (float(*)[66])smem;
#pragma unroll
    for (int mt = 0; mt < 2; mt++)
#pragma unroll
        for (int nt = 0; nt < 4; nt++) {
            int r0 = mrow + mt * 16 + (lane >> 2);
            int cb = ncol + nt * 8 + 2 * (lane & 3);
            float c0 = fmaf(accc[mt][nt][0], RINV, accm[mt][nt][0]);
            float c1 = fmaf(accc[mt][nt][1], RINV, accm[mt][nt][1]);
            float c2 = fmaf(accc[mt][nt][2], RINV, accm[mt][nt][2]);
            float c3 = fmaf(accc[mt][nt][3], RINV, accm[mt][nt][3]);
            *(float2*)&lg[r0][cb]     = make_float2(c0, c1);
            *(float2*)&lg[r0 + 8][cb] = make_float2(c2, c3);
        }
    __syncthreads();

    if (tid < ROWS_CTA) {
        const float* bs = (const float*)(smem + OFF_BIAS);
        float v0 = -3.402823466e38f, v1 = -3.402823466e38f;
        int i0 = 0, i1 = 0;
#pragma unroll
        for (int e = 0; e < NEXP; e++) {
            float v = fmaf(lg[tid][e], INV_WSCALE, bs[e]);
            if (v > v0) { v1 = v0; i1 = i0; v0 = v; i0 = e; }
            else if (v > v1) { v1 = v; i1 = e; }
        }
        float d  = expf(v1 - v0);
        float p0 = 1.0f / (1.0f + d);
        float p1 = d / (1.0f + d);

        int grow = rowBase + tid;
        float* orow = out + (size_t)grow * NEXP;
#pragma unroll
        for (int gq = 0; gq < NEXP / 4; gq++) {
            float4 ov;
            int e = gq * 4;
            ov.x = (e + 0 == i0) ? p0 : ((e + 0 == i1) ? p1 : 0.0f);
            ov.y = (e + 1 == i0) ? p0 : ((e + 1 == i1) ? p1 : 0.0f);
            ov.z = (e + 2 == i0) ? p0 : ((e + 2 == i1) ? p1 : 0.0f);
            ov.w = (e + 3 == i0) ? p0 : ((e + 3 == i1) ? p1 : 0.0f);
            *(float4*)(orow + e) = ov;
        }
        if (out_size >= NROWS * (NEXP + 2)) {
            float* oidx = out + (size_t)NROWS * NEXP + (size_t)grow * 2;
            oidx[0] = (float)i0;
            oidx[1] = (float)i1;
        }
    }
}

extern "C" void kernel_launch(void* const* d_in, const int* in_sizes, int n_in,
                              void* d_out, int out_size) {
    const float* x = nullptr;
    const float* W = nullptr;
    const float* b = nullptr;
    for (int i = 0; i < n_in; i++) {
        if (in_sizes[i] == NROWS * DIM)      x = (const float*)d_in[i];
        else if (in_sizes[i] == NEXP * DIM)  W = (const float*)d_in[i];
        else if (in_sizes[i] == NEXP)        b = (const float*)d_in[i];
    }
    cudaFuncSetAttribute(gating_mma_kernel, cudaFuncAttributeMaxDynamicSharedMemorySize,
                         SMEM_BYTES);
    prep_kernel<<<128, 256>>>(W);
    gating_mma_kernel<<<NROWS / ROWS_CTA, NTH, SMEM_BYTES>>>(x, b, (float*)d_out, out_size);
}